// round 15
// baseline (speedup 1.0000x reference)
#include <cuda_runtime.h>
#include <cuda_fp16.h>
#include <math.h>
#include <stdint.h>

#define NROWS 4096
#define BHALF 2048
#define D     1024
#define C     12
#define BM    128
#define BN    64
#define NT    32
#define NTILES2 (NT * (NT + 1))     // 1056 subtiles (128x64)
#define NPERS 444                   // 148 SMs x 3 CTAs
#define KCH   32
#define NCH   (D / KCH)             // 32
#define RSTR  40                    // fp16 row stride in halves (80B)

#define SZ_A (BM * RSTR * 2)        // 10240
#define SZ_B (BN * RSTR * 2)        // 5120
#define BUFSZ (2 * SZ_A + 2 * SZ_B) // 30720
#define OFF_AHI 0
#define OFF_ALO (SZ_A)
#define OFF_BHI (2 * SZ_A)
#define OFF_BLO (2 * SZ_A + SZ_B)
#define OFF_ZB  (2 * BUFSZ)
#define OFF_SQB (OFF_ZB + BN * C * 4)
#define SMEM_REQ (OFF_SQB + BN * 4 + 128)   // ~64.9KB

__device__ __half g_hi[(size_t)NROWS * D];
__device__ __half g_lo[(size_t)NROWS * D];
__device__ float  g_sq[NROWS];
__device__ float  g_colpart[128][D];
__device__ float  g_cpart[128][C];
__device__ int    g_prespart[128];
__device__ float  g_fac[2 * C];
__device__ double g_loss;
__device__ float  g_coef;
__device__ int    g_pctr;
__device__ int    g_tilectr;
__device__ int    g_donectr;

static __device__ __forceinline__ uint32_t s2u(const void* p) {
    uint32_t a;
    asm("{ .reg .u64 t; cvta.to.shared.u64 t, %1; cvt.u32.u64 %0, t; }" : "=r"(a) : "l"(p));
    return a;
}

#define CP_ASYNC16(dst, src) \
    asm volatile("cp.async.cg.shared.global [%0], [%1], 16;" :: "r"(dst), "l"(src))
#define CP_COMMIT()  asm volatile("cp.async.commit_group;" ::: "memory")
#define CP_WAIT0()   asm volatile("cp.async.wait_group 0;" ::: "memory")

#define LDSM4(r, a) \
    asm volatile("ldmatrix.sync.aligned.m8n8.x4.shared.b16 {%0,%1,%2,%3}, [%4];" \
        : "=r"((r)[0]), "=r"((r)[1]), "=r"((r)[2]), "=r"((r)[3]) : "r"(a))

static __device__ __forceinline__ void mma_f16(float* c, const uint32_t* a,
                                               uint32_t b0, uint32_t b1) {
    asm volatile(
        "mma.sync.aligned.m16n8k16.row.col.f32.f16.f16.f32 "
        "{%0,%1,%2,%3}, {%4,%5,%6,%7}, {%8,%9}, {%0,%1,%2,%3};"
        : "+f"(c[0]), "+f"(c[1]), "+f"(c[2]), "+f"(c[3])
        : "r"(a[0]), "r"(a[1]), "r"(a[2]), "r"(a[3]), "r"(b0), "r"(b1));
}

// ============== launch 0: fused labels + split + row-sq + colsum + finalize
__global__ void k_prep(const float* __restrict__ src, const float* __restrict__ tgt,
                       const float* __restrict__ sl,  const float* __restrict__ tl) {
    __shared__ float scol[D];
    __shared__ double dr[256];
    __shared__ int lastf;
    const int tid = threadIdx.x, lane = tid & 31, w = tid >> 5;
    const int bid = blockIdx.x;
    const int r0 = bid * 32;
    const bool isSrc = (r0 < BHALF);
    const float* base = isSrc ? src + (size_t)r0 * D : tgt + (size_t)(r0 - BHALF) * D;

    for (int c = tid; c < D; c += 256) scol[c] = 0.f;

    if (w == 0) {
        const float* lp = isSrc ? sl + (size_t)(r0 + lane) * C
                                : tl + (size_t)(r0 - BHALF + lane) * C;
        float v[C];
        float4 q0 = *(const float4*)lp;
        float4 q1 = *(const float4*)(lp + 4);
        float4 q2 = *(const float4*)(lp + 8);
        v[0] = q0.x; v[1] = q0.y; v[2]  = q0.z; v[3]  = q0.w;
        v[4] = q1.x; v[5] = q1.y; v[6]  = q1.z; v[7]  = q1.w;
        v[8] = q2.x; v[9] = q2.y; v[10] = q2.z; v[11] = q2.w;
        int arg = 0; float best = v[0];
        #pragma unroll
        for (int c = 1; c < C; c++) if (v[c] > best) { best = v[c]; arg = c; }
        unsigned pres = __reduce_or_sync(0xffffffffu, 1u << arg);
        #pragma unroll
        for (int c = 0; c < C; c++) {
            #pragma unroll
            for (int o = 16; o > 0; o >>= 1)
                v[c] += __shfl_xor_sync(0xffffffffu, v[c], o);
        }
        if (lane == 0) {
            #pragma unroll
            for (int c = 0; c < C; c++) g_cpart[bid][c] = v[c];
            g_prespart[bid] = (int)pres;
        }
    }
    __syncthreads();

    float4 csum[8];
    #pragma unroll
    for (int j = 0; j < 8; j++) csum[j] = make_float4(0.f, 0.f, 0.f, 0.f);
    #pragma unroll
    for (int t = 0; t < 4; t++) {
        const int rr = w + 8 * t;
        const float* p = base + (size_t)rr * D;
        __half* ph = g_hi + (size_t)(r0 + rr) * D;
        __half* pl = g_lo + (size_t)(r0 + rr) * D;
        float sq = 0.f;
        #pragma unroll
        for (int j = 0; j < 8; j++) {
            const int col = lane * 4 + 128 * j;
            float4 v = *(const float4*)(p + col);
            sq += v.x * v.x + v.y * v.y + v.z * v.z + v.w * v.w;
            csum[j].x += v.x; csum[j].y += v.y; csum[j].z += v.z; csum[j].w += v.w;
            __half h[4], l[4];
            float vv[4] = {v.x, v.y, v.z, v.w};
            #pragma unroll
            for (int q = 0; q < 4; q++) {
                h[q] = __float2half_rn(vv[q]);
                l[q] = __float2half_rn(vv[q] - __half2float(h[q]));
            }
            *(uint2*)(ph + col) = *(uint2*)h;
            *(uint2*)(pl + col) = *(uint2*)l;
        }
        #pragma unroll
        for (int o = 16; o > 0; o >>= 1) sq += __shfl_xor_sync(0xffffffffu, sq, o);
        if (lane == 0) g_sq[r0 + rr] = sq;
    }
    #pragma unroll
    for (int j = 0; j < 8; j++) {
        const int col = lane * 4 + 128 * j;
        atomicAdd(&scol[col + 0], csum[j].x);
        atomicAdd(&scol[col + 1], csum[j].y);
        atomicAdd(&scol[col + 2], csum[j].z);
        atomicAdd(&scol[col + 3], csum[j].w);
    }
    __syncthreads();
    #pragma unroll
    for (int q = 0; q < 4; q++) {
        const int c = tid + 256 * q;
        g_colpart[bid][c] = scol[c];
    }
    __threadfence();
    __syncthreads();
    if (tid == 0) lastf = (atomicAdd(&g_pctr, 1) == 127) ? 1 : 0;
    __syncthreads();
    if (!lastf) return;

    if (tid < C) {
        float ss = 0.f, ts = 0.f;
        int sp = 0, tp = 0;
        for (int b = 0; b < 64; b++)   { ss += g_cpart[b][tid]; sp |= g_prespart[b]; }
        for (int b = 64; b < 128; b++) { ts += g_cpart[b][tid]; tp |= g_prespart[b]; }
        bool common = ((sp >> tid) & 1) && ((tp >> tid) & 1);
        g_fac[tid]     = (common && ss > 0.f) ?  1.f / ss : 0.f;
        g_fac[C + tid] = (common && ts > 0.f) ? -1.f / ts : 0.f;
    }
    double s = 0.0;
    for (int i = tid; i < NROWS; i += 256) s += (double)g_sq[i];
    dr[tid] = s;
    __syncthreads();
    for (int o = 128; o > 0; o >>= 1) {
        if (tid < o) dr[tid] += dr[tid + o];
        __syncthreads();
    }
    double sumsq = dr[0];
    __syncthreads();
    s = 0.0;
    for (int c = tid; c < D; c += 256) {
        float cs = 0.f;
        for (int b = 0; b < 128; b++) cs += g_colpart[b][c];
        s += (double)cs * (double)cs;
    }
    dr[tid] = s;
    __syncthreads();
    for (int o = 128; o > 0; o >>= 1) {
        if (tid < o) dr[tid] += dr[tid + o];
        __syncthreads();
    }
    if (tid == 0) {
        const double n = (double)NROWS;
        double sum_l2 = 2.0 * n * sumsq - 2.0 * dr[0];
        double bw = sum_l2 / (n * n - n) / 4.0;
        g_coef = (float)(-1.0 / (16.0 * bw * 0.6931471805599453));
        g_loss = 0.0;
        g_tilectr = 0;
        g_donectr = 0;
        g_pctr = 0;
    }
}

// ============== launch 1: persistent fp16-split MMA, target 3 CTAs/SM
__global__ __launch_bounds__(256, 3) void k_mmd(const float* __restrict__ sl,
                                                const float* __restrict__ tl,
                                                float* __restrict__ out) {
    extern __shared__ __align__(16) unsigned char sm[];
    float* zB  = (float*)(sm + OFF_ZB);
    float* sqB = (float*)(sm + OFF_SQB);
    __shared__ float red[8];
    __shared__ float s_fac[2 * C];
    __shared__ int s_tile;

    const int tid = threadIdx.x, wid = tid >> 5, lane = tid & 31;
    const int wm = wid >> 1, wn = wid & 1;     // warp grid 4m x 2n; warp = 32 rows x 32 cols
    const int gq = lane >> 2, gr = lane & 3;
    const uint32_t smU = s2u(sm);

    if (tid < 2 * C) s_fac[tid] = g_fac[tid];

    // cp.async map (24KB/chunk): A hi/lo 2 tasks each, B hi/lo 1 task each
    const int srow = tid >> 2, sseg = tid & 3;
    const uint32_t sAH0 = smU + OFF_AHI + (srow * RSTR + sseg * 8) * 2;
    const uint32_t sAH1 = smU + OFF_AHI + ((srow + 64) * RSTR + sseg * 8) * 2;
    const uint32_t sAL0 = smU + OFF_ALO + (srow * RSTR + sseg * 8) * 2;
    const uint32_t sAL1 = smU + OFF_ALO + ((srow + 64) * RSTR + sseg * 8) * 2;
    const uint32_t sBH = smU + OFF_BHI + (srow * RSTR + sseg * 8) * 2;
    const uint32_t sBL = smU + OFF_BLO + (srow * RSTR + sseg * 8) * 2;

    // ldmatrix lane offsets: A rows wm*32.., B rows wn*32..; x4 = 16 rows x 16 halves
    const uint32_t aoff = (((uint32_t)(wm * 32 + (lane & 15))) * RSTR + (lane >> 4) * 8) * 2;
    const uint32_t boff = (((uint32_t)(wn * 32 + (lane & 15))) * RSTR + (lane >> 4) * 8) * 2;

    while (true) {
        if (tid == 0) s_tile = atomicAdd(&g_tilectr, 1);
        __syncthreads();
        const int T = s_tile;
        if (T >= NTILES2) break;

        const int t2 = T >> 1, half = T & 1;
        int L = t2, bi = 0;
        while (L >= NT - bi) { L -= NT - bi; bi++; }
        const int bj = bi + L;
        const int rowA = bi * BM, rowB = bj * BM + half * BN;
        const size_t gA = (size_t)rowA * D, gB = (size_t)rowB * D;

        const __half* pAH = g_hi + gA + (size_t)srow * D + sseg * 8;
        const __half* pAL = g_lo + gA + (size_t)srow * D + sseg * 8;
        const __half* pBH = g_hi + gB + (size_t)srow * D + sseg * 8;
        const __half* pBL = g_lo + gB + (size_t)srow * D + sseg * 8;

    #define STAGE(bo, ko) do {                              \
        CP_ASYNC16(sAH0 + (bo), pAH + (ko));                \
        CP_ASYNC16(sAH1 + (bo), pAH + (ko) + 64 * D);       \
        CP_ASYNC16(sAL0 + (bo), pAL + (ko));                \
        CP_ASYNC16(sAL1 + (bo), pAL + (ko) + 64 * D);       \
        CP_ASYNC16(sBH + (bo), pBH + (ko));                 \
        CP_ASYNC16(sBL + (bo), pBL + (ko));                 \
        CP_COMMIT();                                        \
    } while (0)

        STAGE(0, 0);

        for (int t = tid; t < BN * C; t += 256) {
            const int r = rowB + t / C, c = t % C;
            zB[t] = (r < BHALF) ? sl[(size_t)r * C + c] * s_fac[c]
                                : tl[(size_t)(r - BHALF) * C + c] * s_fac[C + c];
        }
        if (tid < BN) sqB[tid] = g_sq[rowB + tid];

        // acc[m][n]: m = 16-row block (2), n = 8-col block (4) covering 32 cols
        float acc[2][4][4];
        #pragma unroll
        for (int m = 0; m < 2; m++)
            #pragma unroll
            for (int n = 0; n < 4; n++)
                #pragma unroll
                for (int r = 0; r < 4; r++) acc[m][n][r] = 0.f;

        for (int c = 0; c < NCH; c++) {
            const int buf = c & 1;
            CP_WAIT0();
            __syncthreads();
            if (c + 1 < NCH) STAGE((uint32_t)(buf ^ 1) * BUFSZ, (size_t)(c + 1) * KCH);

            const uint32_t bo = (uint32_t)buf * BUFSZ;
            const uint32_t aHi = smU + bo + OFF_AHI + aoff;
            const uint32_t aLo = smU + bo + OFF_ALO + aoff;
            const uint32_t bHi = smU + bo + OFF_BHI + boff;
            const uint32_t bLo = smU + bo + OFF_BLO + boff;

            // ks = k-halves of the 32-wide chunk (16 halves each, kso advances k)
            #pragma unroll
            for (int ks = 0; ks < 2; ks++) {
                const uint32_t kso = ks * 32;           // 16 halves = 32B
                uint32_t ahi[2][4], alo[2][4];
                // A fragments: rows wm*32+{0-15, 16-31}, k16 each
                LDSM4(ahi[0], aHi + kso);
                LDSM4(ahi[1], aHi + kso + 16 * RSTR * 2);
                LDSM4(alo[0], aLo + kso);
                LDSM4(alo[1], aLo + kso + 16 * RSTR * 2);
                // B fragments: rows(cols) wn*32+{0-15, 16-31}, k16 each
                uint32_t bh0[4], bh1[4], bl0[4], bl1[4];
                LDSM4(bh0, bHi + kso);                  // cols 0-15
                LDSM4(bh1, bHi + kso + 16 * RSTR * 2);  // cols 16-31
                LDSM4(bl0, bLo + kso);
                LDSM4(bl1, bLo + kso + 16 * RSTR * 2);
                // ldmatrix.x4 over 16 rows x 16 halves: r0=rows0-7/k0-7,
                // r1=rows8-15/k0-7, r2=rows0-7/k8-15, r3=rows8-15/k8-15
                // m16n8k16 B operand (n8,k16) = {k0-7, k8-15} of one 8-row group:
                //   n-group 0 -> (b[0], b[2]); n-group 1 -> (b[1], b[3])
                #pragma unroll
                for (int m = 0; m < 2; m++) {
                    mma_f16(acc[m][0], ahi[m], bh0[0], bh0[2]);
                    mma_f16(acc[m][1], ahi[m], bh0[1], bh0[3]);
                    mma_f16(acc[m][2], ahi[m], bh1[0], bh1[2]);
                    mma_f16(acc[m][3], ahi[m], bh1[1], bh1[3]);
                    mma_f16(acc[m][0], alo[m], bh0[0], bh0[2]);
                    mma_f16(acc[m][1], alo[m], bh0[1], bh0[3]);
                    mma_f16(acc[m][2], alo[m], bh1[0], bh1[2]);
                    mma_f16(acc[m][3], alo[m], bh1[1], bh1[3]);
                    mma_f16(acc[m][0], ahi[m], bl0[0], bl0[2]);
                    mma_f16(acc[m][1], ahi[m], bl0[1], bl0[3]);
                    mma_f16(acc[m][2], ahi[m], bl1[0], bl1[2]);
                    mma_f16(acc[m][3], ahi[m], bl1[1], bl1[3]);
                }
            }
            __syncthreads();
        }

        // ---- epilogue ----
        const float coef = g_coef;
        float lsum = 0.f;
        #pragma unroll
        for (int m = 0; m < 2; m++) {
            #pragma unroll
            for (int h = 0; h < 2; h++) {
                const int ig = rowA + wm * 32 + m * 16 + gq + 8 * h;
                const float sqi = g_sq[ig];
                const float* zp = (ig < BHALF) ? sl + (size_t)ig * C
                                               : tl + (size_t)(ig - BHALF) * C;
                const int fo = (ig < BHALF) ? 0 : C;
                float zi[C];
                {
                    float4 q0 = *(const float4*)zp;
                    float4 q1 = *(const float4*)(zp + 4);
                    float4 q2 = *(const float4*)(zp + 8);
                    zi[0]  = q0.x * s_fac[fo + 0];  zi[1]  = q0.y * s_fac[fo + 1];
                    zi[2]  = q0.z * s_fac[fo + 2];  zi[3]  = q0.w * s_fac[fo + 3];
                    zi[4]  = q1.x * s_fac[fo + 4];  zi[5]  = q1.y * s_fac[fo + 5];
                    zi[6]  = q1.z * s_fac[fo + 6];  zi[7]  = q1.w * s_fac[fo + 7];
                    zi[8]  = q2.x * s_fac[fo + 8];  zi[9]  = q2.y * s_fac[fo + 9];
                    zi[10] = q2.z * s_fac[fo + 10]; zi[11] = q2.w * s_fac[fo + 11];
                }
                #pragma unroll
                for (int n = 0; n < 4; n++) {
                    #pragma unroll
                    for (int p = 0; p < 2; p++) {
                        const int jl = wn * 32 + n * 8 + 2 * gr + p;
                        const int jg = rowB + jl;
                        const float gv = acc[m][n][2 * h + p];
                        float l2 = fmaxf(fmaf(-2.f, gv, sqi + sqB[jl]), 0.f);
                        float e;
                        asm("ex2.approx.ftz.f32 %0, %1;" : "=f"(e) : "f"(l2 * coef));
                        float e2 = e * e, e4 = e2 * e2, e8 = e4 * e4, e16 = e8 * e8;
                        float ks5 = e + e2 + e4 + e8 + e16;
                        float w = 0.f;
                        #pragma unroll
                        for (int cc = 0; cc < C; cc++) w = fmaf(zi[cc], zB[jl * C + cc], w);
                        const float sc = (jg > ig) ? 2.f : ((jg == ig) ? 1.f : 0.f);
                        lsum = fmaf(sc * w, ks5, lsum);
                    }
                }
            }
        }

        #pragma unroll
        for (int o = 16; o > 0; o >>= 1) lsum += __shfl_xor_sync(0xffffffffu, lsum, o);
        if (lane == 0) red[wid] = lsum;
        __syncthreads();
        if (tid == 0) {
            float s = 0.f;
            #pragma unroll
            for (int w = 0; w < 8; w++) s += red[w];
            atomicAdd(&g_loss, (double)s);
        }
    }

    if (tid == 0) {
        __threadfence();
        int d = atomicAdd(&g_donectr, 1);
        if (d == (int)gridDim.x - 1) {
            float f = (float)(g_loss / 12.0);
            if (!isfinite(f)) f = 0.f;
            out[0] = f;
        }
    }
}

// ================================================================ launch
extern "C" void kernel_launch(void* const* d_in, const int* in_sizes, int n_in,
                              void* d_out, int out_size) {
    const float* src = (const float*)d_in[0];
    const float* tgt = (const float*)d_in[1];
    const float* sl  = (const float*)d_in[2];
    const float* tl  = (const float*)d_in[3];
    float* out = (float*)d_out;

    cudaFuncSetAttribute(k_mmd, cudaFuncAttributeMaxDynamicSharedMemorySize, SMEM_REQ);

    k_prep<<<128, 256>>>(src, tgt, sl, tl);          // launch 0
    k_mmd<<<NPERS, 256, SMEM_REQ>>>(sl, tl, out);    // launch 1
}

// round 16
// speedup vs baseline: 1.2204x; 1.2204x over previous
#include <cuda_runtime.h>
#include <cuda_fp16.h>
#include <math.h>
#include <stdint.h>

#define NROWS 4096
#define BHALF 2048
#define D     1024
#define C     12
#define BM    128
#define BN    64
#define NT    32
#define NTILES2 (NT * (NT + 1))     // 1056 subtiles (128x64)
#define NPERS 296                   // 148 SMs x 2 CTAs, all resident
#define KCH   32
#define NCH   (D / KCH)             // 32
#define RSTR  40                    // fp16 row stride in halves (80B)
#define R8    48                    // int8 row stride in bytes
#define SCALE8 (1.0f / 524288.0f)   // 2^-4 * 2^-15

#define SZ_AHI (BM * RSTR * 2)      // 10240
#define SZ_BHI (BN * RSTR * 2)      // 5120
#define SZ_A8  (BM * R8)            // 6144
#define SZ_B8  (BN * R8)            // 3072
#define BUFSZ  (SZ_AHI + SZ_BHI + 2 * SZ_A8 + 2 * SZ_B8)   // 33792
#define OFF_AHI 0
#define OFF_BHI (SZ_AHI)
#define OFF_A8H (SZ_AHI + SZ_BHI)
#define OFF_A8L (OFF_A8H + SZ_A8)
#define OFF_B8H (OFF_A8L + SZ_A8)
#define OFF_B8L (OFF_B8H + SZ_B8)
#define OFF_ZB  (2 * BUFSZ)
#define OFF_SQB (OFF_ZB + BN * C * 4)
#define SMEM_REQ (OFF_SQB + BN * 4 + 256)

// ---- scratch ----
__device__ __half         g_hi[(size_t)NROWS * D];
__device__ unsigned char  g_h8[(size_t)NROWS * D];
__device__ unsigned char  g_l8[(size_t)NROWS * D];
__device__ float  g_sq[NROWS];
__device__ float  g_colpart[128][D];
__device__ float  g_cpart[128][C];
__device__ int    g_prespart[128];
__device__ float  g_fac[2 * C];
__device__ double g_loss;
__device__ float  g_coef;
__device__ int    g_pctr;
__device__ int    g_tilectr;
__device__ int    g_donectr;
__device__ int    g_ready;
__device__ int    g_slabready[128];

static __device__ __forceinline__ uint32_t s2u(const void* p) {
    uint32_t a;
    asm("{ .reg .u64 t; cvta.to.shared.u64 t, %1; cvt.u32.u64 %0, t; }" : "=r"(a) : "l"(p));
    return a;
}

#define CP_ASYNC16(dst, src) \
    asm volatile("cp.async.cg.shared.global [%0], [%1], 16;" :: "r"(dst), "l"(src))
#define CP_COMMIT()  asm volatile("cp.async.commit_group;" ::: "memory")
#define CP_WAIT0()   asm volatile("cp.async.wait_group 0;" ::: "memory")

#define LDSM4(r, a) \
    asm volatile("ldmatrix.sync.aligned.m8n8.x4.shared.b16 {%0,%1,%2,%3}, [%4];" \
        : "=r"((r)[0]), "=r"((r)[1]), "=r"((r)[2]), "=r"((r)[3]) : "r"(a))

static __device__ __forceinline__ void mma_f16(float* c, const uint32_t* a,
                                               uint32_t b0, uint32_t b1) {
    asm volatile(
        "mma.sync.aligned.m16n8k16.row.col.f32.f16.f16.f32 "
        "{%0,%1,%2,%3}, {%4,%5,%6,%7}, {%8,%9}, {%0,%1,%2,%3};"
        : "+f"(c[0]), "+f"(c[1]), "+f"(c[2]), "+f"(c[3])
        : "r"(a[0]), "r"(a[1]), "r"(a[2]), "r"(a[3]), "r"(b0), "r"(b1));
}

static __device__ __forceinline__ void mma_s8(int* c, const uint32_t* a,
                                              uint32_t b0, uint32_t b1) {
    asm volatile(
        "mma.sync.aligned.m16n8k32.row.col.s32.s8.s8.s32 "
        "{%0,%1,%2,%3}, {%4,%5,%6,%7}, {%8,%9}, {%0,%1,%2,%3};"
        : "+r"(c[0]), "+r"(c[1]), "+r"(c[2]), "+r"(c[3])
        : "r"(a[0]), "r"(a[1]), "r"(a[2]), "r"(a[3]), "r"(b0), "r"(b1));
}

static __device__ __forceinline__ int clamp127(int v) {
    return v < -127 ? -127 : (v > 127 ? 127 : v);
}

// ================= single fused persistent kernel =================
__global__ __launch_bounds__(256, 2) void k_all(
    const float* __restrict__ src, const float* __restrict__ tgt,
    const float* __restrict__ sl,  const float* __restrict__ tl,
    float* __restrict__ out
) {
    extern __shared__ __align__(16) unsigned char sm[];
    float* zB  = (float*)(sm + OFF_ZB);
    float* sqB = (float*)(sm + OFF_SQB);
    __shared__ float red[8];
    __shared__ float s_fac[2 * C];
    __shared__ int s_tile;
    __shared__ int s_lastf;
    __shared__ int s_fl;

    const int tid = threadIdx.x, wid = tid >> 5, lane = tid & 31;
    const int bid = blockIdx.x;
    const uint32_t smU = s2u(sm);

    if (tid == 0) s_fl = 0;

    // ================= phase 0: prep (first 128 CTAs) =================
    if (bid < 128) {
        float* scol = (float*)sm;               // 4KB
        double* dr  = (double*)(sm + 4096);     // 2KB
        const int w = wid;
        const int r0 = bid * 32;
        const bool isSrc = (r0 < BHALF);
        const float* base = isSrc ? src + (size_t)r0 * D : tgt + (size_t)(r0 - BHALF) * D;

        for (int c = tid; c < D; c += 256) scol[c] = 0.f;

        if (w == 0) {
            const float* lp = isSrc ? sl + (size_t)(r0 + lane) * C
                                    : tl + (size_t)(r0 - BHALF + lane) * C;
            float v[C];
            float4 q0 = *(const float4*)lp;
            float4 q1 = *(const float4*)(lp + 4);
            float4 q2 = *(const float4*)(lp + 8);
            v[0] = q0.x; v[1] = q0.y; v[2]  = q0.z; v[3]  = q0.w;
            v[4] = q1.x; v[5] = q1.y; v[6]  = q1.z; v[7]  = q1.w;
            v[8] = q2.x; v[9] = q2.y; v[10] = q2.z; v[11] = q2.w;
            int arg = 0; float best = v[0];
            #pragma unroll
            for (int c = 1; c < C; c++) if (v[c] > best) { best = v[c]; arg = c; }
            unsigned pres = __reduce_or_sync(0xffffffffu, 1u << arg);
            #pragma unroll
            for (int c = 0; c < C; c++) {
                #pragma unroll
                for (int o = 16; o > 0; o >>= 1)
                    v[c] += __shfl_xor_sync(0xffffffffu, v[c], o);
            }
            if (lane == 0) {
                #pragma unroll
                for (int c = 0; c < C; c++) g_cpart[bid][c] = v[c];
                g_prespart[bid] = (int)pres;
            }
        }
        __syncthreads();

        float4 csum[8];
        #pragma unroll
        for (int j = 0; j < 8; j++) csum[j] = make_float4(0.f, 0.f, 0.f, 0.f);
        #pragma unroll
        for (int t = 0; t < 4; t++) {
            const int rr = w + 8 * t;
            const float* p = base + (size_t)rr * D;
            __half* ph = g_hi + (size_t)(r0 + rr) * D;
            unsigned char* p8h = g_h8 + (size_t)(r0 + rr) * D;
            unsigned char* p8l = g_l8 + (size_t)(r0 + rr) * D;
            float sq = 0.f;
            #pragma unroll
            for (int j = 0; j < 8; j++) {
                const int col = lane * 4 + 128 * j;
                float4 v = *(const float4*)(p + col);
                sq += v.x * v.x + v.y * v.y + v.z * v.z + v.w * v.w;
                csum[j].x += v.x; csum[j].y += v.y; csum[j].z += v.z; csum[j].w += v.w;
                __half h[4];
                float vv[4] = {v.x, v.y, v.z, v.w};
                uint32_t hp = 0, lp = 0;
                #pragma unroll
                for (int q = 0; q < 4; q++) {
                    h[q] = __float2half_rn(vv[q]);
                    float hf = __half2float(h[q]);
                    float lf = vv[q] - hf;
                    int qh = clamp127(__float2int_rn(hf * 16.f));
                    int ql = clamp127(__float2int_rn(lf * 32768.f));
                    hp |= ((uint32_t)qh & 0xFFu) << (8 * q);
                    lp |= ((uint32_t)ql & 0xFFu) << (8 * q);
                }
                *(uint2*)(ph + col) = *(uint2*)h;
                *(uint32_t*)(p8h + col) = hp;
                *(uint32_t*)(p8l + col) = lp;
            }
            #pragma unroll
            for (int o = 16; o > 0; o >>= 1) sq += __shfl_xor_sync(0xffffffffu, sq, o);
            if (lane == 0) g_sq[r0 + rr] = sq;
        }
        #pragma unroll
        for (int j = 0; j < 8; j++) {
            const int col = lane * 4 + 128 * j;
            atomicAdd(&scol[col + 0], csum[j].x);
            atomicAdd(&scol[col + 1], csum[j].y);
            atomicAdd(&scol[col + 2], csum[j].z);
            atomicAdd(&scol[col + 3], csum[j].w);
        }
        __syncthreads();
        #pragma unroll
        for (int q = 0; q < 4; q++) {
            const int c = tid + 256 * q;
            g_colpart[bid][c] = scol[c];
        }
        __threadfence();
        __syncthreads();
        if (tid == 0) {
            atomicExch(&g_slabready[bid], 1);
            s_lastf = (atomicAdd(&g_pctr, 1) == 127) ? 1 : 0;
        }
        __syncthreads();

        if (s_lastf) {
            // ---- finalize: factors + bandwidth ----
            if (tid < C) {
                float ss = 0.f, ts = 0.f;
                int sp = 0, tp = 0;
                for (int b = 0; b < 64; b++)   { ss += g_cpart[b][tid]; sp |= g_prespart[b]; }
                for (int b = 64; b < 128; b++) { ts += g_cpart[b][tid]; tp |= g_prespart[b]; }
                bool common = ((sp >> tid) & 1) && ((tp >> tid) & 1);
                g_fac[tid]     = (common && ss > 0.f) ?  1.f / ss : 0.f;
                g_fac[C + tid] = (common && ts > 0.f) ? -1.f / ts : 0.f;
            }
            double s = 0.0;
            for (int i = tid; i < NROWS; i += 256) s += (double)g_sq[i];
            dr[tid] = s;
            __syncthreads();
            for (int o = 128; o > 0; o >>= 1) {
                if (tid < o) dr[tid] += dr[tid + o];
                __syncthreads();
            }
            double sumsq = dr[0];
            __syncthreads();
            s = 0.0;
            for (int c = tid; c < D; c += 256) {
                float cs = 0.f;
                for (int b = 0; b < 128; b++) cs += g_colpart[b][c];
                s += (double)cs * (double)cs;
            }
            dr[tid] = s;
            __syncthreads();
            for (int o = 128; o > 0; o >>= 1) {
                if (tid < o) dr[tid] += dr[tid + o];
                __syncthreads();
            }
            if (tid == 0) {
                const double n = (double)NROWS;
                double sum_l2 = 2.0 * n * sumsq - 2.0 * dr[0];
                double bw = sum_l2 / (n * n - n) / 4.0;
                g_coef = (float)(-1.0 / (16.0 * bw * 0.6931471805599453));
            }
            __syncthreads();
            __threadfence();
            __syncthreads();
            if (tid == 0) atomicExch(&g_ready, 1);
        }
        __syncthreads();
    }

    // ================= phase 1: persistent MMA tile loop =================
    const int wm = wid >> 1, wn = wid & 1;
    const int gq = lane >> 2, gr = lane & 3;

    const uint32_t sA0 = smU + OFF_AHI + ((tid >> 2) * RSTR + (tid & 3) * 8) * 2;
    const uint32_t sA1 = smU + OFF_AHI + (((tid >> 2) + 64) * RSTR + (tid & 3) * 8) * 2;
    const uint32_t sB0 = smU + OFF_BHI + ((tid >> 2) * RSTR + (tid & 3) * 8) * 2;
    const uint32_t s8a = (tid >> 1) * R8 + (tid & 1) * 16;
    const uint32_t s8AH = smU + OFF_A8H + s8a;
    const uint32_t s8AL = smU + OFF_A8L + s8a;
    const uint32_t s8B = smU + ((tid < 128) ? OFF_B8H : OFF_B8L)
                       + ((tid & 127) >> 1) * R8 + (tid & 1) * 16;

    const uint32_t aoffH = (((uint32_t)(wm * 32 + (lane & 15))) * RSTR + (lane >> 4) * 8) * 2;
    const uint32_t boffH = (((uint32_t)(wn * 32 + (lane & 7) + ((lane >> 4) * 8))) * RSTR
                           + ((lane >> 3) & 1) * 8) * 2;
    const uint32_t aoff8 = (uint32_t)(wm * 32 + (lane & 15)) * R8 + (lane >> 4) * 16;
    const uint32_t boff8 = (uint32_t)(wn * 32 + (lane & 15)) * R8 + (lane >> 4) * 16;

    int seen_all = 0;

    while (true) {
        if (tid == 0) s_tile = atomicAdd(&g_tilectr, 1);
        __syncthreads();
        const int T = s_tile;
        if (T >= NTILES2) break;

        const int t2 = T >> 1, half = T & 1;
        int L = t2, bi = 0;
        while (L >= NT - bi) { L -= NT - bi; bi++; }
        const int bj = bi + L;
        const int rowA = bi * BM, rowB = bj * BM + half * BN;
        const size_t gA = (size_t)rowA * D, gB = (size_t)rowB * D;

        // wait for required data slabs (prep overlap)
        if (tid == 0 && !seen_all) {
            if (*(volatile int*)&g_ready) {
                seen_all = 1;
            } else {
                const int sa = rowA >> 5, sb = rowB >> 5;
                #pragma unroll
                for (int q = 0; q < 4; q++)
                    while (!*(volatile int*)&g_slabready[sa + q]) { }
                #pragma unroll
                for (int q = 0; q < 2; q++)
                    while (!*(volatile int*)&g_slabready[sb + q]) { }
            }
            __threadfence();
        }
        __syncthreads();

        const __half* pA0 = g_hi + gA + (size_t)(tid >> 2) * D + (tid & 3) * 8;
        const __half* pA1 = pA0 + (size_t)64 * D;
        const __half* pB0 = g_hi + gB + (size_t)(tid >> 2) * D + (tid & 3) * 8;
        const size_t o8a = (size_t)(tid >> 1) * D + (tid & 1) * 16;
        const unsigned char* p8AH = g_h8 + gA + o8a;
        const unsigned char* p8AL = g_l8 + gA + o8a;
        const unsigned char* p8B = ((tid < 128) ? g_h8 : g_l8) + gB
                                 + (size_t)((tid & 127) >> 1) * D + (tid & 1) * 16;

    #define STAGE(bo, ko) do {                          \
        CP_ASYNC16(sA0 + (bo), pA0 + (ko));             \
        CP_ASYNC16(sA1 + (bo), pA1 + (ko));             \
        CP_ASYNC16(sB0 + (bo), pB0 + (ko));             \
        CP_ASYNC16(s8AH + (bo), p8AH + (ko));           \
        CP_ASYNC16(s8AL + (bo), p8AL + (ko));           \
        CP_ASYNC16(s8B + (bo), p8B + (ko));             \
        CP_COMMIT();                                    \
    } while (0)

        STAGE(0, 0);

        // stage raw labels (no fac needed yet) + sq
        for (int t = tid; t < BN * C; t += 256) {
            const int r = rowB + t / C, c = t % C;
            zB[t] = (r < BHALF) ? sl[(size_t)r * C + c] : tl[(size_t)(r - BHALF) * C + c];
        }
        if (tid < BN) sqB[tid] = g_sq[rowB + tid];

        float accf[2][4][4];
        int   acci[2][4][4];
        #pragma unroll
        for (int m = 0; m < 2; m++)
            #pragma unroll
            for (int n = 0; n < 4; n++)
                #pragma unroll
                for (int r = 0; r < 4; r++) { accf[m][n][r] = 0.f; acci[m][n][r] = 0; }

        for (int c = 0; c < NCH; c++) {
            const int buf = c & 1;
            CP_WAIT0();
            __syncthreads();
            if (c + 1 < NCH) STAGE((uint32_t)(buf ^ 1) * BUFSZ, (size_t)(c + 1) * KCH);

            const uint32_t bo = (uint32_t)buf * BUFSZ;
            const uint32_t aHi = smU + bo + OFF_AHI + aoffH;
            const uint32_t bHi = smU + bo + OFF_BHI + boffH;
            const uint32_t a8H = smU + bo + OFF_A8H + aoff8;
            const uint32_t a8L = smU + bo + OFF_A8L + aoff8;
            const uint32_t b8H = smU + bo + OFF_B8H + boff8;
            const uint32_t b8L = smU + bo + OFF_B8L + boff8;

            #pragma unroll
            for (int ks = 0; ks < 2; ks++) {
                const uint32_t kso = ks * 32;
                uint32_t ah[2][4], bh0[4], bh1[4];
                LDSM4(ah[0], aHi + kso);
                LDSM4(ah[1], aHi + kso + 16 * RSTR * 2);
                LDSM4(bh0, bHi + kso);
                LDSM4(bh1, bHi + kso + 16 * RSTR * 2);
                #pragma unroll
                for (int m = 0; m < 2; m++) {
                    mma_f16(accf[m][0], ah[m], bh0[0], bh0[1]);
                    mma_f16(accf[m][1], ah[m], bh0[2], bh0[3]);
                    mma_f16(accf[m][2], ah[m], bh1[0], bh1[1]);
                    mma_f16(accf[m][3], ah[m], bh1[2], bh1[3]);
                }
            }
            {
                uint32_t a8h[2][4], a8l[2][4], b8h0[4], b8h1[4], b8l0[4], b8l1[4];
                LDSM4(a8h[0], a8H);
                LDSM4(a8h[1], a8H + 16 * R8);
                LDSM4(a8l[0], a8L);
                LDSM4(a8l[1], a8L + 16 * R8);
                LDSM4(b8h0, b8H);
                LDSM4(b8h1, b8H + 16 * R8);
                LDSM4(b8l0, b8L);
                LDSM4(b8l1, b8L + 16 * R8);
                #pragma unroll
                for (int m = 0; m < 2; m++) {
                    mma_s8(acci[m][0], a8h[m], b8l0[0], b8l0[2]);
                    mma_s8(acci[m][0], a8l[m], b8h0[0], b8h0[2]);
                    mma_s8(acci[m][1], a8h[m], b8l0[1], b8l0[3]);
                    mma_s8(acci[m][1], a8l[m], b8h0[1], b8h0[3]);
                    mma_s8(acci[m][2], a8h[m], b8l1[0], b8l1[2]);
                    mma_s8(acci[m][2], a8l[m], b8h1[0], b8h1[2]);
                    mma_s8(acci[m][3], a8h[m], b8l1[1], b8l1[3]);
                    mma_s8(acci[m][3], a8l[m], b8h1[1], b8h1[3]);
                }
            }
        }

        // ---- one-time: wait for finalize, load factors ----
        if (!s_fl) {
            if (tid == 0) {
                while (!*(volatile int*)&g_ready) { }
                __threadfence();
            }
            __syncthreads();
            if (tid < 2 * C) s_fac[tid] = g_fac[tid];
            if (tid == 0) s_fl = 1;
            __syncthreads();
        }

        // ---- epilogue: zB holds raw labels; fold facI*facJ into zi ----
        const float coef = g_coef;
        const int foJ = (rowB < BHALF) ? 0 : C;
        float lsum = 0.f;
        #pragma unroll
        for (int m = 0; m < 2; m++) {
            #pragma unroll
            for (int h = 0; h < 2; h++) {
                const int ig = rowA + wm * 32 + m * 16 + gq + 8 * h;
                const float sqi = g_sq[ig];
                const float* zp = (ig < BHALF) ? sl + (size_t)ig * C
                                               : tl + (size_t)(ig - BHALF) * C;
                const int foI = (ig < BHALF) ? 0 : C;
                float zi[C];
                {
                    float4 q0 = *(const float4*)zp;
                    float4 q1 = *(const float4*)(zp + 4);
                    float4 q2 = *(const float4*)(zp + 8);
                    float raw[C] = {q0.x, q0.y, q0.z, q0.w,
                                    q1.x, q1.y, q1.z, q1.w,
                                    q2.x, q2.y, q2.z, q2.w};
                    #pragma unroll
                    for (int cc = 0; cc < C; cc++)
                        zi[cc] = raw[cc] * s_fac[foI + cc] * s_fac[foJ + cc];
                }
                #pragma unroll
                for (int n = 0; n < 4; n++) {
                    #pragma unroll
                    for (int p = 0; p < 2; p++) {
                        const int jl = wn * 32 + n * 8 + 2 * gr + p;
                        const int jg = rowB + jl;
                        const float gv = accf[m][n][2 * h + p]
                                       + (float)acci[m][n][2 * h + p] * SCALE8;
                        float l2 = fmaxf(fmaf(-2.f, gv, sqi + sqB[jl]), 0.f);
                        float e;
                        asm("ex2.approx.ftz.f32 %0, %1;" : "=f"(e) : "f"(l2 * coef));
                        float e2 = e * e, e4 = e2 * e2, e8 = e4 * e4, e16 = e8 * e8;
                        float ks5 = e + e2 + e4 + e8 + e16;
                        float w = 0.f;
                        #pragma unroll
                        for (int cc = 0; cc < C; cc++) w = fmaf(zi[cc], zB[jl * C + cc], w);
                        const float sc = (jg > ig) ? 2.f : ((jg == ig) ? 1.f : 0.f);
                        lsum = fmaf(sc * w, ks5, lsum);
                    }
                }
            }
        }

        #pragma unroll
        for (int o = 16; o > 0; o >>= 1) lsum += __shfl_xor_sync(0xffffffffu, lsum, o);
        if (lane == 0) red[wid] = lsum;
        __syncthreads();
        if (tid == 0) {
            float s = 0.f;
            #pragma unroll
            for (int w = 0; w < 8; w++) s += red[w];
            atomicAdd(&g_loss, (double)s);
        }
    }

    // ---- last CTA: write output, reset state for next graph replay ----
    if (tid == 0) {
        __threadfence();
        int d = atomicAdd(&g_donectr, 1);
        if (d == (int)gridDim.x - 1) {
            double lv = g_loss;
            float f = (float)(lv / 12.0);
            if (!isfinite(f)) f = 0.f;
            g_loss = 0.0;
            g_pctr = 0;
            g_tilectr = 0;
            g_donectr = 0;
            g_ready = 0;
            for (int s = 0; s < 128; s++) g_slabready[s] = 0;
            out[0] = f;
        }
    }
}

// ================================================================ launch
extern "C" void kernel_launch(void* const* d_in, const int* in_sizes, int n_in,
                              void* d_out, int out_size) {
    const float* src = (const float*)d_in[0];
    const float* tgt = (const float*)d_in[1];
    const float* sl  = (const float*)d_in[2];
    const float* tl  = (const float*)d_in[3];
    float* out = (float*)d_out;

    cudaFuncSetAttribute(k_all, cudaFuncAttributeMaxDynamicSharedMemorySize, SMEM_REQ);

    k_all<<<NPERS, 256, SMEM_REQ>>>(src, tgt, sl, tl, out);
}